// round 1
// baseline (speedup 1.0000x reference)
#include <cuda_runtime.h>
#include <cstdint>

// Shapes (fixed by the problem)
#define BATCH   16
#define SEQ     2048
#define M_ROWS  (BATCH * SEQ)   // 32768
#define KDIM    1024
#define NDIM    1024            // P == APP == 1024

// ---------------- scratch (device globals: allocation-free rule) ------------
__device__ float g_xp[(size_t)M_ROWS * NDIM];   // relu(x@Wp^T) unnormalized, 128 MiB
__device__ float g_inv[M_ROWS];                 // 1/(||row||+eps)
__device__ float g_ws[BATCH * NDIM];            // sum_n m*inv*xp
__device__ float g_att[M_ROWS];
__device__ float g_msum[BATCH];

__device__ __forceinline__ float to_tf32(float x) {
    float y;
    asm("cvt.rna.tf32.f32 %0, %1;" : "=f"(y) : "f"(x));
    return y;
}

__device__ __forceinline__ void mma_tf32(float c[4], const uint32_t a[4], const uint32_t b[2]) {
    asm volatile(
        "mma.sync.aligned.m16n8k8.row.col.f32.tf32.tf32.f32 "
        "{%0,%1,%2,%3}, {%4,%5,%6,%7}, {%8,%9}, {%0,%1,%2,%3};\n"
        : "+f"(c[0]), "+f"(c[1]), "+f"(c[2]), "+f"(c[3])
        : "r"(a[0]), "r"(a[1]), "r"(a[2]), "r"(a[3]), "r"(b[0]), "r"(b[1]));
}

// ---------------- GEMM: C = relu(A @ W^T + bias) [* att]  ------------------
// A: [M_ROWS, KDIM] row-major, W: [NDIM, KDIM] row-major.
// Block tile 128x128, BK=16, 8 warps (2x4), warp tile 64x32 via m16n8k8 tf32.
template<bool SCALE>
__global__ __launch_bounds__(256, 2) void gemm_relu_kernel(
    const float* __restrict__ A,
    const float* __restrict__ W,
    const float* __restrict__ bias,
    float* __restrict__ Cout)            // used when SCALE; else writes g_xp
{
    __shared__ float As[128][20];   // [row][k], +4 pad: conflict-free frag reads
    __shared__ float Bs[128][20];   // [n][k]

    const int tid    = threadIdx.x;
    const int warpId = tid >> 5;
    const int lane   = tid & 31;
    const int wm     = warpId >> 2;   // 0..1
    const int wn     = warpId & 3;    // 0..3
    const int g      = lane >> 2;     // 0..7
    const int tg     = lane & 3;      // 0..3

    const int rowBlock = blockIdx.y * 128;
    const int colBlock = blockIdx.x * 128;

    float acc[4][4][4];
    #pragma unroll
    for (int mi = 0; mi < 4; mi++)
        #pragma unroll
        for (int ni = 0; ni < 4; ni++)
            #pragma unroll
            for (int r = 0; r < 4; r++) acc[mi][ni][r] = 0.f;

    const int lr = tid >> 2;          // 0..63
    const int lc = (tid & 3) * 4;     // 0,4,8,12

    for (int k0 = 0; k0 < KDIM; k0 += 16) {
        float4 a0 = *(const float4*)&A[(size_t)(rowBlock + lr)      * KDIM + k0 + lc];
        float4 a1 = *(const float4*)&A[(size_t)(rowBlock + lr + 64) * KDIM + k0 + lc];
        float4 b0 = *(const float4*)&W[(size_t)(colBlock + lr)      * KDIM + k0 + lc];
        float4 b1 = *(const float4*)&W[(size_t)(colBlock + lr + 64) * KDIM + k0 + lc];

        __syncthreads();  // previous tile's reads done
        a0.x = to_tf32(a0.x); a0.y = to_tf32(a0.y); a0.z = to_tf32(a0.z); a0.w = to_tf32(a0.w);
        a1.x = to_tf32(a1.x); a1.y = to_tf32(a1.y); a1.z = to_tf32(a1.z); a1.w = to_tf32(a1.w);
        b0.x = to_tf32(b0.x); b0.y = to_tf32(b0.y); b0.z = to_tf32(b0.z); b0.w = to_tf32(b0.w);
        b1.x = to_tf32(b1.x); b1.y = to_tf32(b1.y); b1.z = to_tf32(b1.z); b1.w = to_tf32(b1.w);
        *(float4*)&As[lr]      [lc] = a0;
        *(float4*)&As[lr + 64] [lc] = a1;
        *(float4*)&Bs[lr]      [lc] = b0;
        *(float4*)&Bs[lr + 64] [lc] = b1;
        __syncthreads();

        #pragma unroll
        for (int kk = 0; kk < 16; kk += 8) {
            uint32_t af[4][4];
            #pragma unroll
            for (int mi = 0; mi < 4; mi++) {
                int r = wm * 64 + mi * 16 + g;
                af[mi][0] = __float_as_uint(As[r    ][kk + tg]);
                af[mi][1] = __float_as_uint(As[r + 8][kk + tg]);
                af[mi][2] = __float_as_uint(As[r    ][kk + tg + 4]);
                af[mi][3] = __float_as_uint(As[r + 8][kk + tg + 4]);
            }
            uint32_t bf[4][2];
            #pragma unroll
            for (int ni = 0; ni < 4; ni++) {
                int c = wn * 32 + ni * 8 + g;
                bf[ni][0] = __float_as_uint(Bs[c][kk + tg]);
                bf[ni][1] = __float_as_uint(Bs[c][kk + tg + 4]);
            }
            #pragma unroll
            for (int mi = 0; mi < 4; mi++)
                #pragma unroll
                for (int ni = 0; ni < 4; ni++)
                    mma_tf32(acc[mi][ni], af[mi], bf[ni]);
        }
    }

    // Epilogue: bias + relu (+ att scale), float2 stores
    #pragma unroll
    for (int mi = 0; mi < 4; mi++) {
        int r0 = rowBlock + wm * 64 + mi * 16 + g;
        int r1 = r0 + 8;
        float s0 = 1.f, s1 = 1.f;
        if (SCALE) { s0 = g_att[r0]; s1 = g_att[r1]; }
        #pragma unroll
        for (int ni = 0; ni < 4; ni++) {
            int c0 = colBlock + wn * 32 + ni * 8 + tg * 2;
            float bb0 = bias[c0], bb1 = bias[c0 + 1];
            float v00 = fmaxf(acc[mi][ni][0] + bb0, 0.f);
            float v01 = fmaxf(acc[mi][ni][1] + bb1, 0.f);
            float v10 = fmaxf(acc[mi][ni][2] + bb0, 0.f);
            float v11 = fmaxf(acc[mi][ni][3] + bb1, 0.f);
            if (SCALE) {
                float2 w0 = make_float2(v00 * s0, v01 * s0);
                float2 w1 = make_float2(v10 * s1, v11 * s1);
                *(float2*)&Cout[(size_t)r0 * NDIM + c0] = w0;
                *(float2*)&Cout[(size_t)r1 * NDIM + c0] = w1;
            } else {
                *(float2*)&g_xp[(size_t)r0 * NDIM + c0] = make_float2(v00, v01);
                *(float2*)&g_xp[(size_t)r1 * NDIM + c0] = make_float2(v10, v11);
            }
        }
    }
}

// ---------------- row inverse norms ----------------------------------------
__global__ void rownorm_kernel() {
    int row  = blockIdx.x * 8 + (threadIdx.x >> 5);
    int lane = threadIdx.x & 31;
    const float* p = g_xp + (size_t)row * NDIM;
    float ss = 0.f;
    #pragma unroll 8
    for (int i = lane; i < NDIM; i += 32) { float v = p[i]; ss += v * v; }
    #pragma unroll
    for (int o = 16; o > 0; o >>= 1) ss += __shfl_xor_sync(0xffffffffu, ss, o);
    if (lane == 0) g_inv[row] = 1.f / (sqrtf(ss) + 1e-8f);
}

// ---------------- mask row sums (msum[b] = sum_n mask[n,b]) -----------------
__global__ void msum_kernel(const float* __restrict__ mask) {
    int w = threadIdx.x >> 5, lane = threadIdx.x & 31;
    if (w >= BATCH) return;
    float s = 0.f;
    for (int n = lane; n < SEQ; n += 32) s += mask[n * BATCH + w];
    #pragma unroll
    for (int o = 16; o > 0; o >>= 1) s += __shfl_xor_sync(0xffffffffu, s, o);
    if (lane == 0) g_msum[w] = s;
}

__global__ void zero_ws_kernel() {
    g_ws[blockIdx.x * 1024 + threadIdx.x] = 0.f;
}

// ---------------- ws[b,p] = sum_n mask[n,b]*inv[b,n]*xp[b,n,p] ---------------
__global__ void ws_kernel(const float* __restrict__ mask) {
    __shared__ float coef[256];
    int b   = blockIdx.x;           // 0..15
    int n0  = blockIdx.y * 256;     // 8 chunks
    int tid = threadIdx.x;          // 256
    coef[tid] = mask[(n0 + tid) * BATCH + b] * g_inv[b * SEQ + n0 + tid];
    __syncthreads();
    float acc[4] = {0.f, 0.f, 0.f, 0.f};
    const float* base = g_xp + (size_t)(b * SEQ + n0) * NDIM;
    for (int j = 0; j < 256; j++) {
        float cf = coef[j];
        const float* r = base + (size_t)j * NDIM;
        #pragma unroll
        for (int i = 0; i < 4; i++) acc[i] += cf * r[tid + i * 256];
    }
    #pragma unroll
    for (int i = 0; i < 4; i++) atomicAdd(&g_ws[b * NDIM + tid + i * 256], acc[i]);
}

// ---------------- att[b,n] = inv * <xp_row, ws_b> / msum[b] -----------------
__global__ void att_kernel() {
    int row  = blockIdx.x * 8 + (threadIdx.x >> 5);
    int lane = threadIdx.x & 31;
    int b    = row >> 11;  // /SEQ
    const float* xr = g_xp + (size_t)row * NDIM;
    const float* w  = g_ws + b * NDIM;
    float d = 0.f;
    #pragma unroll 8
    for (int i = lane; i < NDIM; i += 32) d += xr[i] * w[i];
    #pragma unroll
    for (int o = 16; o > 0; o >>= 1) d += __shfl_xor_sync(0xffffffffu, d, o);
    if (lane == 0) g_att[row] = g_inv[row] * d / g_msum[b];
}

// ---------------- launch ----------------------------------------------------
extern "C" void kernel_launch(void* const* d_in, const int* in_sizes, int n_in,
                              void* d_out, int out_size) {
    const float* x    = (const float*)d_in[0];  // [B,N,D]
    const float* mask = (const float*)d_in[1];  // [N,B]
    const float* Wp   = (const float*)d_in[2];  // [1024,D]
    const float* bp   = (const float*)d_in[3];
    const float* Wv   = (const float*)d_in[4];  // [1024,D]
    const float* bv   = (const float*)d_in[5];
    float* out = (float*)d_out;

    dim3 ggrid(NDIM / 128, M_ROWS / 128);   // (8, 256)
    dim3 gblk(256);

    gemm_relu_kernel<false><<<ggrid, gblk>>>(x, Wp, bp, nullptr);
    rownorm_kernel<<<M_ROWS / 8, 256>>>();
    msum_kernel<<<1, 512>>>(mask);
    zero_ws_kernel<<<BATCH, 1024>>>();
    ws_kernel<<<dim3(BATCH, SEQ / 256), 256>>>(mask);
    att_kernel<<<M_ROWS / 8, 256>>>();
    gemm_relu_kernel<true><<<ggrid, gblk>>>(x, Wv, bv, out);
}

// round 3
// speedup vs baseline: 1.1254x; 1.1254x over previous
#include <cuda_runtime.h>
#include <cstdint>

// Shapes (fixed)
#define BATCH   16
#define SEQ     2048
#define M_ROWS  (BATCH * SEQ)   // 32768
#define KDIM    1024
#define NDIM    1024

// GEMM tiling: block 128x128, BK=16, 3-stage cp.async pipeline
#define BK          16
#define NCHUNKS     (KDIM / BK)         // 64
#define NST         3
#define ROW_F       20                  // 16 floats + 4 pad (conflict-free)
#define A_STAGE_F   (128 * ROW_F)       // 2560 floats = 10240 B
#define STAGE_F     (2 * A_STAGE_F)     // A + B
#define SMEM_FLOATS (NST * STAGE_F)     // 15360 floats = 61440 B

// ---------------- scratch -----------------------------------------------
__device__ float g_xtf[(size_t)M_ROWS * KDIM];   // tf32-rounded x
__device__ float g_wptf[NDIM * KDIM];
__device__ float g_wvtf[NDIM * KDIM];
__device__ float g_xp[(size_t)M_ROWS * NDIM];
__device__ float g_inv[M_ROWS];
__device__ float g_ws[BATCH * NDIM];
__device__ float g_att[M_ROWS];
__device__ float g_msum[BATCH];

// ---------------- helpers ------------------------------------------------
__device__ __forceinline__ uint32_t smem_u32(const void* p) {
    uint32_t a;
    asm("{ .reg .u64 t; cvta.to.shared.u64 t, %1; cvt.u32.u64 %0, t; }" : "=r"(a) : "l"(p));
    return a;
}
__device__ __forceinline__ void mma_tf32(float c[4], const uint32_t a[4], const uint32_t b[2]) {
    asm volatile(
        "mma.sync.aligned.m16n8k8.row.col.f32.tf32.tf32.f32 "
        "{%0,%1,%2,%3}, {%4,%5,%6,%7}, {%8,%9}, {%0,%1,%2,%3};\n"
        : "+f"(c[0]), "+f"(c[1]), "+f"(c[2]), "+f"(c[3])
        : "r"(a[0]), "r"(a[1]), "r"(a[2]), "r"(a[3]), "r"(b[0]), "r"(b[1]));
}
__device__ __forceinline__ void cp16(uint32_t dst, const void* src) {
    asm volatile("cp.async.cg.shared.global [%0], [%1], 16;" :: "r"(dst), "l"(src) : "memory");
}
__device__ __forceinline__ void cp_commit() { asm volatile("cp.async.commit_group;" ::: "memory"); }
__device__ __forceinline__ void cp_wait1()  { asm volatile("cp.async.wait_group 1;" ::: "memory"); }
__device__ __forceinline__ void cp_wait0()  { asm volatile("cp.async.wait_group 0;" ::: "memory"); }

// ---------------- pipelined tf32 GEMM: C = relu(A@W^T + b)[*att] --------
// A: [M_ROWS,KDIM] tf32-rounded, W: [NDIM,KDIM] tf32-rounded.
template<bool SCALE>
__global__ __launch_bounds__(256, 2) void gemm_relu_kernel(
    const float* __restrict__ A,
    const float* __restrict__ W,
    const float* __restrict__ bias,
    float* __restrict__ Cout)
{
    extern __shared__ float smemf[];
    const uint32_t sb = smem_u32(smemf);

    const int tid    = threadIdx.x;
    const int warpId = tid >> 5;
    const int lane   = tid & 31;
    const int wm     = warpId >> 2;   // 0..1
    const int wn     = warpId & 3;    // 0..3
    const int g      = lane >> 2;     // 0..7
    const int tg     = lane & 3;      // 0..3

    const int rowBlock = blockIdx.y * 128;
    const int colBlock = blockIdx.x * 128;

    float acc[4][4][4];
    #pragma unroll
    for (int mi = 0; mi < 4; mi++)
        #pragma unroll
        for (int ni = 0; ni < 4; ni++)
            #pragma unroll
            for (int r = 0; r < 4; r++) acc[mi][ni][r] = 0.f;

    const int lrow = tid >> 2;        // 0..63 (plus +64 on j=1)
    const int lkc  = tid & 3;         // 16B chunk within row

    auto load_stage = [&](int ck, int slot) {
        const uint32_t base = sb + slot * (STAGE_F * 4);
        const size_t koff = (size_t)ck * BK + lkc * 4;
        #pragma unroll
        for (int j = 0; j < 2; j++) {
            const int row = lrow + 64 * j;
            cp16(base + row * (ROW_F * 4) + lkc * 16,
                 A + (size_t)(rowBlock + row) * KDIM + koff);
            cp16(base + (A_STAGE_F * 4) + row * (ROW_F * 4) + lkc * 16,
                 W + (size_t)(colBlock + row) * KDIM + koff);
        }
        cp_commit();
    };

    load_stage(0, 0);
    load_stage(1, 1);

    for (int ks = 0; ks < NCHUNKS; ks++) {
        if (ks < NCHUNKS - 1) cp_wait1(); else cp_wait0();
        __syncthreads();   // stage ks visible to all; iter ks-1 compute done by all

        if (ks + 2 < NCHUNKS) load_stage(ks + 2, (ks + 2) % NST);

        const float* As = smemf + (ks % NST) * STAGE_F;
        const float* Bs = As + A_STAGE_F;

        #pragma unroll
        for (int kk = 0; kk < BK; kk += 8) {
            uint32_t af[4][4];
            #pragma unroll
            for (int mi = 0; mi < 4; mi++) {
                const int r = wm * 64 + mi * 16 + g;
                af[mi][0] = __float_as_uint(As[r * ROW_F + kk + tg]);
                af[mi][1] = __float_as_uint(As[(r + 8) * ROW_F + kk + tg]);
                af[mi][2] = __float_as_uint(As[r * ROW_F + kk + tg + 4]);
                af[mi][3] = __float_as_uint(As[(r + 8) * ROW_F + kk + tg + 4]);
            }
            uint32_t bf[4][2];
            #pragma unroll
            for (int ni = 0; ni < 4; ni++) {
                const int c = wn * 32 + ni * 8 + g;
                bf[ni][0] = __float_as_uint(Bs[c * ROW_F + kk + tg]);
                bf[ni][1] = __float_as_uint(Bs[c * ROW_F + kk + tg + 4]);
            }
            #pragma unroll
            for (int mi = 0; mi < 4; mi++)
                #pragma unroll
                for (int ni = 0; ni < 4; ni++)
                    mma_tf32(acc[mi][ni], af[mi], bf[ni]);
        }
    }

    // Epilogue: bias + relu (+ att scale)
    #pragma unroll
    for (int mi = 0; mi < 4; mi++) {
        const int r0 = rowBlock + wm * 64 + mi * 16 + g;
        const int r1 = r0 + 8;
        float s0 = 1.f, s1 = 1.f;
        if (SCALE) { s0 = g_att[r0]; s1 = g_att[r1]; }
        #pragma unroll
        for (int ni = 0; ni < 4; ni++) {
            const int c0 = colBlock + wn * 32 + ni * 8 + tg * 2;
            const float bb0 = bias[c0], bb1 = bias[c0 + 1];
            float v00 = fmaxf(acc[mi][ni][0] + bb0, 0.f);
            float v01 = fmaxf(acc[mi][ni][1] + bb1, 0.f);
            float v10 = fmaxf(acc[mi][ni][2] + bb0, 0.f);
            float v11 = fmaxf(acc[mi][ni][3] + bb1, 0.f);
            if (SCALE) {
                *(float2*)&Cout[(size_t)r0 * NDIM + c0] = make_float2(v00 * s0, v01 * s0);
                *(float2*)&Cout[(size_t)r1 * NDIM + c0] = make_float2(v10 * s1, v11 * s1);
            } else {
                *(float2*)&g_xp[(size_t)r0 * NDIM + c0] = make_float2(v00, v01);
                *(float2*)&g_xp[(size_t)r1 * NDIM + c0] = make_float2(v10, v11);
            }
        }
    }
}

// ---------------- tf32 rounding pre-pass --------------------------------
__global__ void cvt_tf32_kernel(const float* __restrict__ src, float* __restrict__ dst, int n4) {
    int i = blockIdx.x * blockDim.x + threadIdx.x;
    if (i >= n4) return;
    float4 v = ((const float4*)src)[i];
    asm("cvt.rna.tf32.f32 %0, %0;" : "+f"(v.x));
    asm("cvt.rna.tf32.f32 %0, %0;" : "+f"(v.y));
    asm("cvt.rna.tf32.f32 %0, %0;" : "+f"(v.z));
    asm("cvt.rna.tf32.f32 %0, %0;" : "+f"(v.w));
    ((float4*)dst)[i] = v;
}

// ---------------- aux kernels (unchanged, proven) ------------------------
__global__ void rownorm_kernel() {
    int row = blockIdx.x * 8 + (threadIdx.x >> 5);
    int lane = threadIdx.x & 31;
    const float* p = g_xp + (size_t)row * NDIM;
    float ss = 0.f;
    #pragma unroll 8
    for (int i = lane; i < NDIM; i += 32) { float v = p[i]; ss += v * v; }
    #pragma unroll
    for (int o = 16; o > 0; o >>= 1) ss += __shfl_xor_sync(0xffffffffu, ss, o);
    if (lane == 0) g_inv[row] = 1.f / (sqrtf(ss) + 1e-8f);
}
__global__ void msum_kernel(const float* __restrict__ mask) {
    int w = threadIdx.x >> 5, lane = threadIdx.x & 31;
    if (w >= BATCH) return;
    float s = 0.f;
    for (int n = lane; n < SEQ; n += 32) s += mask[n * BATCH + w];
    #pragma unroll
    for (int o = 16; o > 0; o >>= 1) s += __shfl_xor_sync(0xffffffffu, s, o);
    if (lane == 0) g_msum[w] = s;
}
__global__ void zero_ws_kernel() { g_ws[blockIdx.x * 1024 + threadIdx.x] = 0.f; }
__global__ void ws_kernel(const float* __restrict__ mask) {
    __shared__ float coef[256];
    int b = blockIdx.x, n0 = blockIdx.y * 256, tid = threadIdx.x;
    coef[tid] = mask[(n0 + tid) * BATCH + b] * g_inv[b * SEQ + n0 + tid];
    __syncthreads();
    float acc[4] = {0.f, 0.f, 0.f, 0.f};
    const float* base = g_xp + (size_t)(b * SEQ + n0) * NDIM;
    for (int j = 0; j < 256; j++) {
        float cf = coef[j];
        const float* r = base + (size_t)j * NDIM;
        #pragma unroll
        for (int i = 0; i < 4; i++) acc[i] += cf * r[tid + i * 256];
    }
    #pragma unroll
    for (int i = 0; i < 4; i++) atomicAdd(&g_ws[b * NDIM + tid + i * 256], acc[i]);
}
__global__ void att_kernel() {
    int row = blockIdx.x * 8 + (threadIdx.x >> 5);
    int lane = threadIdx.x & 31;
    int b = row >> 11;
    const float* xr = g_xp + (size_t)row * NDIM;
    const float* w  = g_ws + b * NDIM;
    float d = 0.f;
    #pragma unroll 8
    for (int i = lane; i < NDIM; i += 32) d += xr[i] * w[i];
    #pragma unroll
    for (int o = 16; o > 0; o >>= 1) d += __shfl_xor_sync(0xffffffffu, d, o);
    if (lane == 0) g_att[row] = g_inv[row] * d / g_msum[b];
}

// ---------------- launch -------------------------------------------------
extern "C" void kernel_launch(void* const* d_in, const int* in_sizes, int n_in,
                              void* d_out, int out_size) {
    const float* x    = (const float*)d_in[0];
    const float* mask = (const float*)d_in[1];
    const float* Wp   = (const float*)d_in[2];
    const float* bp   = (const float*)d_in[3];
    const float* Wv   = (const float*)d_in[4];
    const float* bv   = (const float*)d_in[5];
    float* out = (float*)d_out;

    const int smem_bytes = SMEM_FLOATS * 4;   // 61440
    cudaFuncSetAttribute(gemm_relu_kernel<false>, cudaFuncAttributeMaxDynamicSharedMemorySize, smem_bytes);
    cudaFuncSetAttribute(gemm_relu_kernel<true>,  cudaFuncAttributeMaxDynamicSharedMemorySize, smem_bytes);

    float *xtf, *wptf, *wvtf;
    cudaGetSymbolAddress((void**)&xtf,  g_xtf);
    cudaGetSymbolAddress((void**)&wptf, g_wptf);
    cudaGetSymbolAddress((void**)&wvtf, g_wvtf);

    cvt_tf32_kernel<<<(M_ROWS * (KDIM / 4)) / 256, 256>>>(x,  xtf,  M_ROWS * (KDIM / 4));
    cvt_tf32_kernel<<<(NDIM * (KDIM / 4)) / 256, 256>>>(Wp, wptf, NDIM * (KDIM / 4));
    cvt_tf32_kernel<<<(NDIM * (KDIM / 4)) / 256, 256>>>(Wv, wvtf, NDIM * (KDIM / 4));

    dim3 ggrid(NDIM / 128, M_ROWS / 128);   // (8, 256)
    gemm_relu_kernel<false><<<ggrid, 256, smem_bytes>>>(xtf, wptf, bp, nullptr);
    rownorm_kernel<<<M_ROWS / 8, 256>>>();
    msum_kernel<<<1, 512>>>(mask);
    zero_ws_kernel<<<BATCH, 1024>>>();
    ws_kernel<<<dim3(BATCH, SEQ / 256), 256>>>(mask);
    att_kernel<<<M_ROWS / 8, 256>>>();
    gemm_relu_kernel<true><<<ggrid, 256, smem_bytes>>>(xtf, wvtf, bv, out);
}

// round 4
// speedup vs baseline: 1.4763x; 1.3119x over previous
#include <cuda_runtime.h>
#include <cstdint>

// Shapes (fixed)
#define BATCH   16
#define SEQ     2048
#define M_ROWS  (BATCH * SEQ)   // 32768
#define KDIM    1024
#define NDIM    1024

// GEMM tiling: block 128x128, BK=32 (4 kb of 8), 3-stage cp.async pipeline
#define BK          32
#define NCHUNKS     (KDIM / BK)         // 32
#define NST         3
#define A_STAGE_B   16384               // 8 m16 * 4 kb * 32 lanes * 16B
#define B_STAGE_B   16384               // 16 n8 * 4 kb * 32 lanes * 8B
#define STAGE_B     (A_STAGE_B + B_STAGE_B)   // 32768
#define SMEM_BYTES  (NST * STAGE_B)           // 98304

// ---------------- scratch -----------------------------------------------
__device__ float g_xf [(size_t)M_ROWS * KDIM];   // x, tf32-rounded, A-frag-major
__device__ float g_wpf[NDIM * KDIM];             // Wp, B-frag-major
__device__ float g_wvf[NDIM * KDIM];             // Wv, B-frag-major
__device__ float g_xp [(size_t)M_ROWS * NDIM];
__device__ float g_ss [M_ROWS];                  // sum of squares per row
__device__ float g_inv[M_ROWS];
__device__ float g_ws [BATCH * NDIM];
__device__ float g_att[M_ROWS];
__device__ float g_msum[BATCH];

// ---------------- helpers ------------------------------------------------
__device__ __forceinline__ uint32_t smem_u32(const void* p) {
    uint32_t a;
    asm("{ .reg .u64 t; cvta.to.shared.u64 t, %1; cvt.u32.u64 %0, t; }" : "=r"(a) : "l"(p));
    return a;
}
__device__ __forceinline__ void mma_tf32(float c[4], const uint32_t a[4], const uint32_t b[2]) {
    asm volatile(
        "mma.sync.aligned.m16n8k8.row.col.f32.tf32.tf32.f32 "
        "{%0,%1,%2,%3}, {%4,%5,%6,%7}, {%8,%9}, {%0,%1,%2,%3};\n"
        : "+f"(c[0]), "+f"(c[1]), "+f"(c[2]), "+f"(c[3])
        : "r"(a[0]), "r"(a[1]), "r"(a[2]), "r"(a[3]), "r"(b[0]), "r"(b[1]));
}
__device__ __forceinline__ void cp16(uint32_t dst, const void* src) {
    asm volatile("cp.async.cg.shared.global [%0], [%1], 16;" :: "r"(dst), "l"(src) : "memory");
}
__device__ __forceinline__ void cp_commit() { asm volatile("cp.async.commit_group;" ::: "memory"); }
__device__ __forceinline__ void cp_wait1()  { asm volatile("cp.async.wait_group 1;" ::: "memory"); }
__device__ __forceinline__ void cp_wait0()  { asm volatile("cp.async.wait_group 0;" ::: "memory"); }
__device__ __forceinline__ float rna_tf32(float x) {
    asm("cvt.rna.tf32.f32 %0, %0;" : "+f"(x));
    return x;
}

// ---------------- pipelined tf32 GEMM (fragment-major operands) ----------
// A frag-major: float4 idx ((m16*128 + kb)*32 + lane) -> {a0,a1,a2,a3}
// B frag-major: float2 idx ((n8 *128 + kb)*32 + lane) -> {b0,b1}
template<bool SCALE>
__global__ __launch_bounds__(256, 2) void gemm_relu_kernel(
    const float* __restrict__ Af,
    const float* __restrict__ Bf,
    const float* __restrict__ bias,
    float* __restrict__ Cout)
{
    extern __shared__ float smemf[];
    const uint32_t sb = smem_u32(smemf);

    const int tid    = threadIdx.x;
    const int warpId = tid >> 5;
    const int lane   = tid & 31;
    const int wm     = warpId >> 2;   // 0..1
    const int wn     = warpId & 3;    // 0..3
    const int g      = lane >> 2;
    const int tg     = lane & 3;

    const int rowBlock = blockIdx.y * 128;
    const int colBlock = blockIdx.x * 128;
    const int m16base  = rowBlock >> 4;   // global m16 tile
    const int n8base   = colBlock >> 3;   // global n8 tile

    float acc[4][4][4];
    #pragma unroll
    for (int mi = 0; mi < 4; mi++)
        #pragma unroll
        for (int ni = 0; ni < 4; ni++)
            #pragma unroll
            for (int r = 0; r < 4; r++) acc[mi][ni][r] = 0.f;

    // Loader: per stage, A = 1024 chunks of 16B, B = 1024 chunks of 16B.
    auto load_stage = [&](int ck, int slot) {
        const uint32_t base = sb + slot * STAGE_B;
        const int kb0 = ck * 4;
        #pragma unroll
        for (int j = 0; j < 4; j++) {       // A chunks
            const int i    = tid + j * 256;           // 0..1023
            const int m16l = i >> 7;
            const int kbl  = (i >> 5) & 3;
            const int ln   = i & 31;
            const size_t src = ((size_t)((m16base + m16l) * 128 + kb0 + kbl) * 32 + ln) * 4;
            cp16(base + i * 16, Af + src);
        }
        #pragma unroll
        for (int j = 0; j < 4; j++) {       // B chunks
            const int i   = tid + j * 256;            // 0..1023
            const int n8l = i >> 6;
            const int kbl = (i >> 4) & 3;
            const int jj  = i & 15;
            const size_t src = ((size_t)((n8base + n8l) * 128 + kb0 + kbl) * 32 + jj * 2) * 2;
            cp16(base + A_STAGE_B + i * 16, Bf + src);
        }
        cp_commit();
    };

    load_stage(0, 0);
    load_stage(1, 1);

    for (int ks = 0; ks < NCHUNKS; ks++) {
        if (ks < NCHUNKS - 1) cp_wait1(); else cp_wait0();
        __syncthreads();

        if (ks + 2 < NCHUNKS) load_stage(ks + 2, (ks + 2) % NST);

        const float* sA = smemf + (ks % NST) * (STAGE_B / 4);
        const float* sB = sA + (A_STAGE_B / 4);

        #pragma unroll
        for (int kb = 0; kb < 4; kb++) {
            uint32_t af[4][4];
            #pragma unroll
            for (int mi = 0; mi < 4; mi++) {
                const float4 v = *(const float4*)&sA[(((wm * 4 + mi) * 4 + kb) * 32 + lane) * 4];
                af[mi][0] = __float_as_uint(v.x);
                af[mi][1] = __float_as_uint(v.y);
                af[mi][2] = __float_as_uint(v.z);
                af[mi][3] = __float_as_uint(v.w);
            }
            uint32_t bf[4][2];
            #pragma unroll
            for (int ni = 0; ni < 4; ni++) {
                const float2 v = *(const float2*)&sB[(((wn * 4 + ni) * 4 + kb) * 32 + lane) * 2];
                bf[ni][0] = __float_as_uint(v.x);
                bf[ni][1] = __float_as_uint(v.y);
            }
            #pragma unroll
            for (int mi = 0; mi < 4; mi++)
                #pragma unroll
                for (int ni = 0; ni < 4; ni++)
                    mma_tf32(acc[mi][ni], af[mi], bf[ni]);
        }
    }

    // Epilogue: bias + relu (+att scale) ; GEMM1 also accumulates row sum-sq.
    #pragma unroll
    for (int mi = 0; mi < 4; mi++) {
        const int r0 = rowBlock + wm * 64 + mi * 16 + g;
        const int r1 = r0 + 8;
        float s0 = 1.f, s1 = 1.f;
        if (SCALE) { s0 = g_att[r0]; s1 = g_att[r1]; }
        float ss0 = 0.f, ss1 = 0.f;
        #pragma unroll
        for (int ni = 0; ni < 4; ni++) {
            const int c0 = colBlock + wn * 32 + ni * 8 + tg * 2;
            const float bb0 = bias[c0], bb1 = bias[c0 + 1];
            float v00 = fmaxf(acc[mi][ni][0] + bb0, 0.f);
            float v01 = fmaxf(acc[mi][ni][1] + bb1, 0.f);
            float v10 = fmaxf(acc[mi][ni][2] + bb0, 0.f);
            float v11 = fmaxf(acc[mi][ni][3] + bb1, 0.f);
            if (SCALE) {
                *(float2*)&Cout[(size_t)r0 * NDIM + c0] = make_float2(v00 * s0, v01 * s0);
                *(float2*)&Cout[(size_t)r1 * NDIM + c0] = make_float2(v10 * s1, v11 * s1);
            } else {
                ss0 += v00 * v00 + v01 * v01;
                ss1 += v10 * v10 + v11 * v11;
                *(float2*)&g_xp[(size_t)r0 * NDIM + c0] = make_float2(v00, v01);
                *(float2*)&g_xp[(size_t)r1 * NDIM + c0] = make_float2(v10, v11);
            }
        }
        if (!SCALE) {
            ss0 += __shfl_xor_sync(0xffffffffu, ss0, 1);
            ss0 += __shfl_xor_sync(0xffffffffu, ss0, 2);
            ss1 += __shfl_xor_sync(0xffffffffu, ss1, 1);
            ss1 += __shfl_xor_sync(0xffffffffu, ss1, 2);
            if (tg == 0) {
                atomicAdd(&g_ss[r0], ss0);
                atomicAdd(&g_ss[r1], ss1);
            }
        }
    }
}

// ---------------- converters: tf32 round + fragment-major permute --------
// A: one thread -> one output float4 {a0,a1,a2,a3}
__global__ void cvtA_kernel(const float* __restrict__ x) {
    const int i    = blockIdx.x * blockDim.x + threadIdx.x;  // float4 index
    const int lane = i & 31;
    const int kb   = (i >> 5) & 127;
    const int m16  = i >> 12;
    const int row0 = m16 * 16 + (lane >> 2);
    const int c0   = kb * 8 + (lane & 3);
    float4 v;
    v.x = rna_tf32(x[(size_t)row0 * KDIM + c0]);
    v.y = rna_tf32(x[(size_t)(row0 + 8) * KDIM + c0]);
    v.z = rna_tf32(x[(size_t)row0 * KDIM + c0 + 4]);
    v.w = rna_tf32(x[(size_t)(row0 + 8) * KDIM + c0 + 4]);
    ((float4*)g_xf)[i] = v;
}
// B: one thread -> one output float2 {b0,b1}
__global__ void cvtB_kernel(const float* __restrict__ W, float* __restrict__ dst) {
    const int i    = blockIdx.x * blockDim.x + threadIdx.x;  // float2 index
    const int lane = i & 31;
    const int kb   = (i >> 5) & 127;
    const int n8   = i >> 12;
    const int col  = n8 * 8 + (lane >> 2);
    const int c0   = kb * 8 + (lane & 3);
    float2 v;
    v.x = rna_tf32(W[(size_t)col * KDIM + c0]);
    v.y = rna_tf32(W[(size_t)col * KDIM + c0 + 4]);
    ((float2*)dst)[i] = v;
}

// ---------------- aux kernels --------------------------------------------
__global__ void zero_kernel() {
    const int i = blockIdx.x * 1024 + threadIdx.x;
    if (i < M_ROWS) g_ss[i] = 0.f;
    if (i < BATCH * NDIM) g_ws[i] = 0.f;
}
__global__ void inv_kernel() {
    const int i = blockIdx.x * 256 + threadIdx.x;
    g_inv[i] = 1.f / (sqrtf(g_ss[i]) + 1e-8f);
}
__global__ void msum_kernel(const float* __restrict__ mask) {
    int w = threadIdx.x >> 5, lane = threadIdx.x & 31;
    if (w >= BATCH) return;
    float s = 0.f;
    for (int n = lane; n < SEQ; n += 32) s += mask[n * BATCH + w];
    #pragma unroll
    for (int o = 16; o > 0; o >>= 1) s += __shfl_xor_sync(0xffffffffu, s, o);
    if (lane == 0) g_msum[w] = s;
}
__global__ void ws_kernel(const float* __restrict__ mask) {
    __shared__ float coef[256];
    int b = blockIdx.x, n0 = blockIdx.y * 256, tid = threadIdx.x;
    coef[tid] = mask[(n0 + tid) * BATCH + b] * g_inv[b * SEQ + n0 + tid];
    __syncthreads();
    float acc[4] = {0.f, 0.f, 0.f, 0.f};
    const float* base = g_xp + (size_t)(b * SEQ + n0) * NDIM;
    for (int j = 0; j < 256; j++) {
        float cf = coef[j];
        const float* r = base + (size_t)j * NDIM;
        #pragma unroll
        for (int i = 0; i < 4; i++) acc[i] += cf * r[tid + i * 256];
    }
    #pragma unroll
    for (int i = 0; i < 4; i++) atomicAdd(&g_ws[b * NDIM + tid + i * 256], acc[i]);
}
__global__ void att_kernel() {
    int row = blockIdx.x * 8 + (threadIdx.x >> 5);
    int lane = threadIdx.x & 31;
    int b = row >> 11;
    const float* xr = g_xp + (size_t)row * NDIM;
    const float* w  = g_ws + b * NDIM;
    float d = 0.f;
    #pragma unroll 8
    for (int i = lane; i < NDIM; i += 32) d += xr[i] * w[i];
    #pragma unroll
    for (int o = 16; o > 0; o >>= 1) d += __shfl_xor_sync(0xffffffffu, d, o);
    if (lane == 0) g_att[row] = g_inv[row] * d / g_msum[b];
}

// ---------------- launch -------------------------------------------------
extern "C" void kernel_launch(void* const* d_in, const int* in_sizes, int n_in,
                              void* d_out, int out_size) {
    const float* x    = (const float*)d_in[0];
    const float* mask = (const float*)d_in[1];
    const float* Wp   = (const float*)d_in[2];
    const float* bp   = (const float*)d_in[3];
    const float* Wv   = (const float*)d_in[4];
    const float* bv   = (const float*)d_in[5];
    float* out = (float*)d_out;

    cudaFuncSetAttribute(gemm_relu_kernel<false>, cudaFuncAttributeMaxDynamicSharedMemorySize, SMEM_BYTES);
    cudaFuncSetAttribute(gemm_relu_kernel<true>,  cudaFuncAttributeMaxDynamicSharedMemorySize, SMEM_BYTES);

    float *xf, *wpf, *wvf;
    cudaGetSymbolAddress((void**)&xf,  g_xf);
    cudaGetSymbolAddress((void**)&wpf, g_wpf);
    cudaGetSymbolAddress((void**)&wvf, g_wvf);

    cvtA_kernel<<<(M_ROWS * KDIM / 4) / 256, 256>>>(x);
    cvtB_kernel<<<(NDIM * KDIM / 2) / 256, 256>>>(Wp, wpf);
    cvtB_kernel<<<(NDIM * KDIM / 2) / 256, 256>>>(Wv, wvf);
    zero_kernel<<<32, 1024>>>();

    dim3 ggrid(NDIM / 128, M_ROWS / 128);   // (8, 256)
    gemm_relu_kernel<false><<<ggrid, 256, SMEM_BYTES>>>(xf, wpf, bp, nullptr);
    inv_kernel<<<M_ROWS / 256, 256>>>();
    msum_kernel<<<1, 512>>>(mask);
    ws_kernel<<<dim3(BATCH, SEQ / 256), 256>>>(mask);
    att_kernel<<<M_ROWS / 8, 256>>>();
    gemm_relu_kernel<true><<<ggrid, 256, SMEM_BYTES>>>(xf, wvf, bv, out);
}

// round 5
// speedup vs baseline: 1.5626x; 1.0584x over previous
#include <cuda_runtime.h>
#include <cstdint>

// Shapes (fixed)
#define BATCH   16
#define SEQ     2048
#define M_ROWS  (BATCH * SEQ)   // 32768
#define KDIM    1024
#define NDIM    1024

// GEMM tiling: block 128x128, BK=32 (4 kb of 8), 3-stage cp.async pipeline
#define BK          32
#define NCHUNKS     (KDIM / BK)         // 32
#define NST         3
#define A_STAGE_B   16384
#define B_STAGE_B   16384
#define STAGE_B     (A_STAGE_B + B_STAGE_B)   // 32768
#define SMEM_BYTES  (NST * STAGE_B)           // 98304

// ---------------- scratch -----------------------------------------------
__device__ float g_xf [(size_t)M_ROWS * KDIM];   // x, tf32-rounded, A-frag-major
__device__ float g_wpf[NDIM * KDIM];             // Wp, B-frag-major
__device__ float g_wvf[NDIM * KDIM];             // Wv, B-frag-major
__device__ float g_xp [(size_t)M_ROWS * NDIM];
__device__ float g_ss [M_ROWS];
__device__ float g_inv[M_ROWS];
__device__ float g_ws [BATCH * NDIM];
__device__ float g_att[M_ROWS];
__device__ float g_msum[BATCH];

// ---------------- helpers ------------------------------------------------
__device__ __forceinline__ uint32_t smem_u32(const void* p) {
    uint32_t a;
    asm("{ .reg .u64 t; cvta.to.shared.u64 t, %1; cvt.u32.u64 %0, t; }" : "=r"(a) : "l"(p));
    return a;
}
__device__ __forceinline__ void mma_tf32(float c[4], const uint32_t a[4], const uint32_t b[2]) {
    asm volatile(
        "mma.sync.aligned.m16n8k8.row.col.f32.tf32.tf32.f32 "
        "{%0,%1,%2,%3}, {%4,%5,%6,%7}, {%8,%9}, {%0,%1,%2,%3};\n"
        : "+f"(c[0]), "+f"(c[1]), "+f"(c[2]), "+f"(c[3])
        : "r"(a[0]), "r"(a[1]), "r"(a[2]), "r"(a[3]), "r"(b[0]), "r"(b[1]));
}
__device__ __forceinline__ void cp16(uint32_t dst, const void* src) {
    asm volatile("cp.async.cg.shared.global [%0], [%1], 16;" :: "r"(dst), "l"(src) : "memory");
}
__device__ __forceinline__ void cp_commit() { asm volatile("cp.async.commit_group;" ::: "memory"); }
__device__ __forceinline__ void cp_wait1()  { asm volatile("cp.async.wait_group 1;" ::: "memory"); }
__device__ __forceinline__ void cp_wait0()  { asm volatile("cp.async.wait_group 0;" ::: "memory"); }
__device__ __forceinline__ float rna_tf32(float x) {
    asm("cvt.rna.tf32.f32 %0, %0;" : "+f"(x));
    return x;
}

// ---------------- pipelined tf32 GEMM (fragment-major operands) ----------
template<bool SCALE>
__global__ __launch_bounds__(256, 2) void gemm_relu_kernel(
    const float* __restrict__ Af,
    const float* __restrict__ Bf,
    const float* __restrict__ bias,
    float* __restrict__ Cout)
{
    extern __shared__ float smemf[];
    const uint32_t sb = smem_u32(smemf);

    const int tid    = threadIdx.x;
    const int warpId = tid >> 5;
    const int lane   = tid & 31;
    const int wm     = warpId >> 2;   // 0..1
    const int wn     = warpId & 3;    // 0..3
    const int g      = lane >> 2;
    const int tg     = lane & 3;

    const int rowBlock = blockIdx.y * 128;
    const int colBlock = blockIdx.x * 128;
    const int m16base  = rowBlock >> 4;
    const int n8base   = colBlock >> 3;

    float acc[4][4][4];
    #pragma unroll
    for (int mi = 0; mi < 4; mi++)
        #pragma unroll
        for (int ni = 0; ni < 4; ni++)
            #pragma unroll
            for (int r = 0; r < 4; r++) acc[mi][ni][r] = 0.f;

    auto load_stage = [&](int ck, int slot) {
        const uint32_t base = sb + slot * STAGE_B;
        const int kb0 = ck * 4;
        #pragma unroll
        for (int j = 0; j < 4; j++) {
            const int i    = tid + j * 256;
            const int m16l = i >> 7;
            const int kbl  = (i >> 5) & 3;
            const int ln   = i & 31;
            const size_t src = ((size_t)((m16base + m16l) * 128 + kb0 + kbl) * 32 + ln) * 4;
            cp16(base + i * 16, Af + src);
        }
        #pragma unroll
        for (int j = 0; j < 4; j++) {
            const int i   = tid + j * 256;
            const int n8l = i >> 6;
            const int kbl = (i >> 4) & 3;
            const int jj  = i & 15;
            const size_t src = ((size_t)((n8base + n8l) * 128 + kb0 + kbl) * 32 + jj * 2) * 2;
            cp16(base + A_STAGE_B + i * 16, Bf + src);
        }
        cp_commit();
    };

    // Per-chunk compute: load kb0 frags FIRST, then (optionally) issue next
    // stage's cp.async, then run MMAs — keeps the LSU free for the first LDS.
    auto compute_chunk = [&](int ks, bool prefetch) {
        const float* sA = smemf + (ks % NST) * (STAGE_B / 4);
        const float* sB = sA + (A_STAGE_B / 4);

        uint32_t af[4][4];
        uint32_t bf[4][2];
        // kb = 0 fragment loads up front
        #pragma unroll
        for (int mi = 0; mi < 4; mi++) {
            const float4 v = *(const float4*)&sA[(((wm * 4 + mi) * 4 + 0) * 32 + lane) * 4];
            af[mi][0] = __float_as_uint(v.x); af[mi][1] = __float_as_uint(v.y);
            af[mi][2] = __float_as_uint(v.z); af[mi][3] = __float_as_uint(v.w);
        }
        #pragma unroll
        for (int ni = 0; ni < 4; ni++) {
            const float2 v = *(const float2*)&sB[(((wn * 4 + ni) * 4 + 0) * 32 + lane) * 2];
            bf[ni][0] = __float_as_uint(v.x); bf[ni][1] = __float_as_uint(v.y);
        }

        if (prefetch) load_stage(ks + 2, (ks + 2) % NST);

        #pragma unroll
        for (int kb = 0; kb < 4; kb++) {
            #pragma unroll
            for (int mi = 0; mi < 4; mi++)
                #pragma unroll
                for (int ni = 0; ni < 4; ni++)
                    mma_tf32(acc[mi][ni], af[mi], bf[ni]);
            if (kb < 3) {
                #pragma unroll
                for (int mi = 0; mi < 4; mi++) {
                    const float4 v = *(const float4*)&sA[(((wm * 4 + mi) * 4 + kb + 1) * 32 + lane) * 4];
                    af[mi][0] = __float_as_uint(v.x); af[mi][1] = __float_as_uint(v.y);
                    af[mi][2] = __float_as_uint(v.z); af[mi][3] = __float_as_uint(v.w);
                }
                #pragma unroll
                for (int ni = 0; ni < 4; ni++) {
                    const float2 v = *(const float2*)&sB[(((wn * 4 + ni) * 4 + kb + 1) * 32 + lane) * 2];
                    bf[ni][0] = __float_as_uint(v.x); bf[ni][1] = __float_as_uint(v.y);
                }
            }
        }
    };

    load_stage(0, 0);
    load_stage(1, 1);

    // Steady state: chunks 0 .. NCHUNKS-3 prefetch ks+2
    for (int ks = 0; ks < NCHUNKS - 2; ks++) {
        cp_wait1();
        __syncthreads();
        compute_chunk(ks, true);
    }
    // Tail: last two chunks, no prefetch
    cp_wait1();
    __syncthreads();
    compute_chunk(NCHUNKS - 2, false);
    cp_wait0();
    __syncthreads();
    compute_chunk(NCHUNKS - 1, false);

    // Epilogue: bias + relu (+att scale); GEMM1 accumulates row sum-sq.
    #pragma unroll
    for (int mi = 0; mi < 4; mi++) {
        const int r0 = rowBlock + wm * 64 + mi * 16 + g;
        const int r1 = r0 + 8;
        float s0 = 1.f, s1 = 1.f;
        if (SCALE) { s0 = g_att[r0]; s1 = g_att[r1]; }
        float ss0 = 0.f, ss1 = 0.f;
        #pragma unroll
        for (int ni = 0; ni < 4; ni++) {
            const int c0 = colBlock + wn * 32 + ni * 8 + tg * 2;
            const float2 bb = *(const float2*)&bias[c0];
            float v00 = fmaxf(acc[mi][ni][0] + bb.x, 0.f);
            float v01 = fmaxf(acc[mi][ni][1] + bb.y, 0.f);
            float v10 = fmaxf(acc[mi][ni][2] + bb.x, 0.f);
            float v11 = fmaxf(acc[mi][ni][3] + bb.y, 0.f);
            if (SCALE) {
                *(float2*)&Cout[(size_t)r0 * NDIM + c0] = make_float2(v00 * s0, v01 * s0);
                *(float2*)&Cout[(size_t)r1 * NDIM + c0] = make_float2(v10 * s1, v11 * s1);
            } else {
                ss0 += v00 * v00 + v01 * v01;
                ss1 += v10 * v10 + v11 * v11;
                *(float2*)&g_xp[(size_t)r0 * NDIM + c0] = make_float2(v00, v01);
                *(float2*)&g_xp[(size_t)r1 * NDIM + c0] = make_float2(v10, v11);
            }
        }
        if (!SCALE) {
            ss0 += __shfl_xor_sync(0xffffffffu, ss0, 1);
            ss0 += __shfl_xor_sync(0xffffffffu, ss0, 2);
            ss1 += __shfl_xor_sync(0xffffffffu, ss1, 1);
            ss1 += __shfl_xor_sync(0xffffffffu, ss1, 2);
            if (tg == 0) {
                atomicAdd(&g_ss[r0], ss0);
                atomicAdd(&g_ss[r1], ss1);
            }
        }
    }
}

// ---------------- converters: tf32 round + fragment-major permute --------
// cvtA also zeroes g_ss and g_ws (removes a separate launch).
__global__ void cvtA_kernel(const float* __restrict__ x) {
    const int i    = blockIdx.x * blockDim.x + threadIdx.x;
    const int lane = i & 31;
    const int kb   = (i >> 5) & 127;
    const int m16  = i >> 12;
    const int row0 = m16 * 16 + (lane >> 2);
    const int c0   = kb * 8 + (lane & 3);
    float4 v;
    v.x = rna_tf32(x[(size_t)row0 * KDIM + c0]);
    v.y = rna_tf32(x[(size_t)(row0 + 8) * KDIM + c0]);
    v.z = rna_tf32(x[(size_t)row0 * KDIM + c0 + 4]);
    v.w = rna_tf32(x[(size_t)(row0 + 8) * KDIM + c0 + 4]);
    ((float4*)g_xf)[i] = v;
    if (i < M_ROWS) g_ss[i] = 0.f;
    if (i < BATCH * NDIM) g_ws[i] = 0.f;
}
__global__ void cvtB_kernel(const float* __restrict__ W, float* __restrict__ dst) {
    const int i    = blockIdx.x * blockDim.x + threadIdx.x;
    const int lane = i & 31;
    const int kb   = (i >> 5) & 127;
    const int n8   = i >> 12;
    const int col  = n8 * 8 + (lane >> 2);
    const int c0   = kb * 8 + (lane & 3);
    float2 v;
    v.x = rna_tf32(W[(size_t)col * KDIM + c0]);
    v.y = rna_tf32(W[(size_t)col * KDIM + c0 + 4]);
    ((float2*)dst)[i] = v;
}

// ---------------- aux kernels --------------------------------------------
__global__ void inv_kernel() {
    const int i = blockIdx.x * 256 + threadIdx.x;
    g_inv[i] = 1.f / (sqrtf(g_ss[i]) + 1e-8f);
}
__global__ void msum_kernel(const float* __restrict__ mask) {
    int w = threadIdx.x >> 5, lane = threadIdx.x & 31;
    if (w >= BATCH) return;
    float s = 0.f;
    for (int n = lane; n < SEQ; n += 32) s += mask[n * BATCH + w];
    #pragma unroll
    for (int o = 16; o > 0; o >>= 1) s += __shfl_xor_sync(0xffffffffu, s, o);
    if (lane == 0) g_msum[w] = s;
}
__global__ void ws_kernel(const float* __restrict__ mask) {
    __shared__ float coef[256];
    int b = blockIdx.x, n0 = blockIdx.y * 256, tid = threadIdx.x;
    coef[tid] = mask[(n0 + tid) * BATCH + b] * g_inv[b * SEQ + n0 + tid];
    __syncthreads();
    float acc[4] = {0.f, 0.f, 0.f, 0.f};
    const float* base = g_xp + (size_t)(b * SEQ + n0) * NDIM;
    for (int j = 0; j < 256; j++) {
        float cf = coef[j];
        const float* r = base + (size_t)j * NDIM;
        #pragma unroll
        for (int i = 0; i < 4; i++) acc[i] += cf * r[tid + i * 256];
    }
    #pragma unroll
    for (int i = 0; i < 4; i++) atomicAdd(&g_ws[b * NDIM + tid + i * 256], acc[i]);
}
__global__ void att_kernel() {
    int row = blockIdx.x * 8 + (threadIdx.x >> 5);
    int lane = threadIdx.x & 31;
    int b = row >> 11;
    const float* xr = g_xp + (size_t)row * NDIM;
    const float* w  = g_ws + b * NDIM;
    float d = 0.f;
    #pragma unroll 8
    for (int i = lane; i < NDIM; i += 32) d += xr[i] * w[i];
    #pragma unroll
    for (int o = 16; o > 0; o >>= 1) d += __shfl_xor_sync(0xffffffffu, d, o);
    if (lane == 0) g_att[row] = g_inv[row] * d / g_msum[b];
}

// ---------------- launch -------------------------------------------------
extern "C" void kernel_launch(void* const* d_in, const int* in_sizes, int n_in,
                              void* d_out, int out_size) {
    const float* x    = (const float*)d_in[0];
    const float* mask = (const float*)d_in[1];
    const float* Wp   = (const float*)d_in[2];
    const float* bp   = (const float*)d_in[3];
    const float* Wv   = (const float*)d_in[4];
    const float* bv   = (const float*)d_in[5];
    float* out = (float*)d_out;

    cudaFuncSetAttribute(gemm_relu_kernel<false>, cudaFuncAttributeMaxDynamicSharedMemorySize, SMEM_BYTES);
    cudaFuncSetAttribute(gemm_relu_kernel<true>,  cudaFuncAttributeMaxDynamicSharedMemorySize, SMEM_BYTES);

    float *xf, *wpf, *wvf;
    cudaGetSymbolAddress((void**)&xf,  g_xf);
    cudaGetSymbolAddress((void**)&wpf, g_wpf);
    cudaGetSymbolAddress((void**)&wvf, g_wvf);

    dim3 ggrid(NDIM / 128, M_ROWS / 128);   // (8, 256)

    cvtA_kernel<<<(M_ROWS * KDIM / 4) / 256, 256>>>(x);               // 0
    cvtB_kernel<<<(NDIM * KDIM / 2) / 256, 256>>>(Wp, wpf);           // 1
    cvtB_kernel<<<(NDIM * KDIM / 2) / 256, 256>>>(Wv, wvf);           // 2
    gemm_relu_kernel<false><<<ggrid, 256, SMEM_BYTES>>>(xf, wpf, bp, nullptr);  // 3
    inv_kernel<<<M_ROWS / 256, 256>>>();                              // 4
    msum_kernel<<<1, 512>>>(mask);                                    // 5
    ws_kernel<<<dim3(BATCH, SEQ / 256), 256>>>(mask);                 // 6
    att_kernel<<<M_ROWS / 8, 256>>>();                                // 7
    gemm_relu_kernel<true><<<ggrid, 256, SMEM_BYTES>>>(xf, wvf, bv, out);  // 8
}

// round 6
// speedup vs baseline: 1.6576x; 1.0609x over previous
#include <cuda_runtime.h>
#include <cstdint>

// Shapes (fixed)
#define BATCH   16
#define SEQ     2048
#define M_ROWS  (BATCH * SEQ)   // 32768
#define KDIM    1024
#define NDIM    1024

// GEMM tiling: block 128x128, 4 warps (warp tile 64x64), BK=32, 3-stage pipe
#define BK          32
#define NCHUNKS     (KDIM / BK)         // 32
#define NST         3
#define A_STAGE_B   16384               // 8 m16 * 4 kb * 32 lanes * 16B
#define B_STAGE_B   16384               // 8 pairs * 4 kb * 32 lanes * 16B
#define STAGE_B     (A_STAGE_B + B_STAGE_B)   // 32768
#define SMEM_BYTES  (NST * STAGE_B)           // 98304

// ---------------- scratch -----------------------------------------------
__device__ float g_xf [(size_t)M_ROWS * KDIM];   // x tf32, A-frag-major
__device__ float g_wpf[NDIM * KDIM];             // Wp tf32, B-pair-frag-major
__device__ float g_wvf[NDIM * KDIM];             // Wv tf32, B-pair-frag-major
__device__ float g_xp [(size_t)M_ROWS * NDIM];
__device__ float g_ss [M_ROWS];
__device__ float g_inv[M_ROWS];
__device__ float g_ws [BATCH * NDIM];
__device__ float g_att[M_ROWS];
__device__ float g_msum[BATCH];

// ---------------- helpers ------------------------------------------------
__device__ __forceinline__ uint32_t smem_u32(const void* p) {
    uint32_t a;
    asm("{ .reg .u64 t; cvta.to.shared.u64 t, %1; cvt.u32.u64 %0, t; }" : "=r"(a) : "l"(p));
    return a;
}
__device__ __forceinline__ void mma_tf32(float c[4], const uint32_t a[4], const uint32_t b[2]) {
    asm volatile(
        "mma.sync.aligned.m16n8k8.row.col.f32.tf32.tf32.f32 "
        "{%0,%1,%2,%3}, {%4,%5,%6,%7}, {%8,%9}, {%0,%1,%2,%3};\n"
        : "+f"(c[0]), "+f"(c[1]), "+f"(c[2]), "+f"(c[3])
        : "r"(a[0]), "r"(a[1]), "r"(a[2]), "r"(a[3]), "r"(b[0]), "r"(b[1]));
}
__device__ __forceinline__ void cp16(uint32_t dst, const void* src) {
    asm volatile("cp.async.cg.shared.global [%0], [%1], 16;" :: "r"(dst), "l"(src) : "memory");
}
__device__ __forceinline__ void cp_commit() { asm volatile("cp.async.commit_group;" ::: "memory"); }
__device__ __forceinline__ void cp_wait1()  { asm volatile("cp.async.wait_group 1;" ::: "memory"); }
__device__ __forceinline__ void cp_wait0()  { asm volatile("cp.async.wait_group 0;" ::: "memory"); }
__device__ __forceinline__ float rna_tf32(float x) {
    asm("cvt.rna.tf32.f32 %0, %0;" : "+f"(x));
    return x;
}

// ---------------- pipelined tf32 GEMM, warp tile 64x64 -------------------
// A frag-major : float4 idx ((m16*128 + kb)*32 + lane) -> {a0,a1,a2,a3}
// B pair-major : float4 idx ((p *128 + kb)*32 + lane) -> {b0,b1 of n8=2p; b0,b1 of n8=2p+1}
template<bool SCALE>
__global__ __launch_bounds__(128, 2) void gemm_relu_kernel(
    const float* __restrict__ Af,
    const float* __restrict__ Bf,
    const float* __restrict__ bias,
    float* __restrict__ Cout)
{
    extern __shared__ float smemf[];
    const uint32_t sb = smem_u32(smemf);

    const int tid    = threadIdx.x;
    const int warpId = tid >> 5;
    const int lane   = tid & 31;
    const int wm     = warpId >> 1;   // 0..1
    const int wn     = warpId & 1;    // 0..1
    const int g      = lane >> 2;
    const int tg     = lane & 3;

    const int rowBlock = blockIdx.y * 128;
    const int colBlock = blockIdx.x * 128;
    const int m16base  = rowBlock >> 4;   // A m16-tile base
    const int p8base   = colBlock >> 4;   // B pair base (16-col units)

    float acc[4][8][4];
    #pragma unroll
    for (int mi = 0; mi < 4; mi++)
        #pragma unroll
        for (int ni = 0; ni < 8; ni++)
            #pragma unroll
            for (int r = 0; r < 4; r++) acc[mi][ni][r] = 0.f;

    auto load_stage = [&](int ck, int slot) {
        const uint32_t base = sb + slot * STAGE_B;
        const int kb0 = ck * 4;
        #pragma unroll
        for (int j = 0; j < 8; j++) {       // A: 1024 chunks of 16B
            const int i    = tid + j * 128;
            const int m16l = i >> 7;
            const int kbl  = (i >> 5) & 3;
            const int ln   = i & 31;
            const size_t src = ((size_t)((m16base + m16l) * 128 + kb0 + kbl) * 32 + ln) * 4;
            cp16(base + i * 16, Af + src);
        }
        #pragma unroll
        for (int j = 0; j < 8; j++) {       // B: 1024 chunks of 16B
            const int i   = tid + j * 128;
            const int pl  = i >> 7;
            const int kbl = (i >> 5) & 3;
            const int ln  = i & 31;
            const size_t src = ((size_t)((p8base + pl) * 128 + kb0 + kbl) * 32 + ln) * 4;
            cp16(base + B_STAGE_B /*A first? no: A at 0*/ * 0 + A_STAGE_B + i * 16, Bf + src);
        }
        cp_commit();
    };

    auto compute_chunk = [&](int ks, bool prefetch) {
        const float* sA = smemf + (ks % NST) * (STAGE_B / 4);
        const float* sB = sA + (A_STAGE_B / 4);

        uint32_t af[4][4];
        uint32_t bf[8][2];
        // kb = 0 fragments up-front (before the cp.async burst)
        #pragma unroll
        for (int mi = 0; mi < 4; mi++) {
            const float4 v = *(const float4*)&sA[(((wm * 4 + mi) * 4 + 0) * 32 + lane) * 4];
            af[mi][0] = __float_as_uint(v.x); af[mi][1] = __float_as_uint(v.y);
            af[mi][2] = __float_as_uint(v.z); af[mi][3] = __float_as_uint(v.w);
        }
        #pragma unroll
        for (int pi = 0; pi < 4; pi++) {
            const float4 v = *(const float4*)&sB[(((wn * 4 + pi) * 4 + 0) * 32 + lane) * 4];
            bf[2 * pi][0]     = __float_as_uint(v.x); bf[2 * pi][1]     = __float_as_uint(v.y);
            bf[2 * pi + 1][0] = __float_as_uint(v.z); bf[2 * pi + 1][1] = __float_as_uint(v.w);
        }

        if (prefetch) load_stage(ks + 2, (ks + 2) % NST);

        #pragma unroll
        for (int kb = 0; kb < 4; kb++) {
            #pragma unroll
            for (int mi = 0; mi < 4; mi++)
                #pragma unroll
                for (int ni = 0; ni < 8; ni++)
                    mma_tf32(acc[mi][ni], af[mi], bf[ni]);
            if (kb < 3) {
                #pragma unroll
                for (int mi = 0; mi < 4; mi++) {
                    const float4 v = *(const float4*)&sA[(((wm * 4 + mi) * 4 + kb + 1) * 32 + lane) * 4];
                    af[mi][0] = __float_as_uint(v.x); af[mi][1] = __float_as_uint(v.y);
                    af[mi][2] = __float_as_uint(v.z); af[mi][3] = __float_as_uint(v.w);
                }
                #pragma unroll
                for (int pi = 0; pi < 4; pi++) {
                    const float4 v = *(const float4*)&sB[(((wn * 4 + pi) * 4 + kb + 1) * 32 + lane) * 4];
                    bf[2 * pi][0]     = __float_as_uint(v.x); bf[2 * pi][1]     = __float_as_uint(v.y);
                    bf[2 * pi + 1][0] = __float_as_uint(v.z); bf[2 * pi + 1][1] = __float_as_uint(v.w);
                }
            }
        }
    };

    load_stage(0, 0);
    load_stage(1, 1);

    for (int ks = 0; ks < NCHUNKS - 2; ks++) {
        cp_wait1();
        __syncthreads();
        compute_chunk(ks, true);
    }
    cp_wait1();
    __syncthreads();
    compute_chunk(NCHUNKS - 2, false);
    cp_wait0();
    __syncthreads();
    compute_chunk(NCHUNKS - 1, false);

    // Epilogue
    #pragma unroll
    for (int mi = 0; mi < 4; mi++) {
        const int r0 = rowBlock + wm * 64 + mi * 16 + g;
        const int r1 = r0 + 8;
        float s0 = 1.f, s1 = 1.f;
        if (SCALE) { s0 = g_att[r0]; s1 = g_att[r1]; }
        float ss0 = 0.f, ss1 = 0.f;
        #pragma unroll
        for (int ni = 0; ni < 8; ni++) {
            const int c0 = colBlock + wn * 64 + ni * 8 + tg * 2;
            const float2 bb = *(const float2*)&bias[c0];
            float v00 = fmaxf(acc[mi][ni][0] + bb.x, 0.f);
            float v01 = fmaxf(acc[mi][ni][1] + bb.y, 0.f);
            float v10 = fmaxf(acc[mi][ni][2] + bb.x, 0.f);
            float v11 = fmaxf(acc[mi][ni][3] + bb.y, 0.f);
            if (SCALE) {
                *(float2*)&Cout[(size_t)r0 * NDIM + c0] = make_float2(v00 * s0, v01 * s0);
                *(float2*)&Cout[(size_t)r1 * NDIM + c0] = make_float2(v10 * s1, v11 * s1);
            } else {
                ss0 += v00 * v00 + v01 * v01;
                ss1 += v10 * v10 + v11 * v11;
                *(float2*)&g_xp[(size_t)r0 * NDIM + c0] = make_float2(v00, v01);
                *(float2*)&g_xp[(size_t)r1 * NDIM + c0] = make_float2(v10, v11);
            }
        }
        if (!SCALE) {
            ss0 += __shfl_xor_sync(0xffffffffu, ss0, 1);
            ss0 += __shfl_xor_sync(0xffffffffu, ss0, 2);
            ss1 += __shfl_xor_sync(0xffffffffu, ss1, 1);
            ss1 += __shfl_xor_sync(0xffffffffu, ss1, 2);
            if (tg == 0) {
                atomicAdd(&g_ss[r0], ss0);
                atomicAdd(&g_ss[r1], ss1);
            }
        }
    }
}

// ---------------- converters ---------------------------------------------
__global__ void cvtA_kernel(const float* __restrict__ x) {
    const int i    = blockIdx.x * blockDim.x + threadIdx.x;   // float4 idx
    const int lane = i & 31;
    const int kb   = (i >> 5) & 127;
    const int m16  = i >> 12;
    const int row0 = m16 * 16 + (lane >> 2);
    const int c0   = kb * 8 + (lane & 3);
    float4 v;
    v.x = rna_tf32(x[(size_t)row0 * KDIM + c0]);
    v.y = rna_tf32(x[(size_t)(row0 + 8) * KDIM + c0]);
    v.z = rna_tf32(x[(size_t)row0 * KDIM + c0 + 4]);
    v.w = rna_tf32(x[(size_t)(row0 + 8) * KDIM + c0 + 4]);
    ((float4*)g_xf)[i] = v;
    if (i < M_ROWS) g_ss[i] = 0.f;
    if (i < BATCH * NDIM) g_ws[i] = 0.f;
}
// B pair-frag-major: float4 idx ((p*128 + kb)*32 + lane)
__global__ void cvtB_kernel(const float* __restrict__ W, float* __restrict__ dst) {
    const int i    = blockIdx.x * blockDim.x + threadIdx.x;   // float4 idx
    const int lane = i & 31;
    const int kb   = (i >> 5) & 127;
    const int p    = i >> 12;                                  // 0..63
    const int col0 = p * 16 + (lane >> 2);                     // n8 = 2p
    const int c0   = kb * 8 + (lane & 3);
    float4 v;
    v.x = rna_tf32(W[(size_t)col0 * KDIM + c0]);
    v.y = rna_tf32(W[(size_t)col0 * KDIM + c0 + 4]);
    v.z = rna_tf32(W[(size_t)(col0 + 8) * KDIM + c0]);
    v.w = rna_tf32(W[(size_t)(col0 + 8) * KDIM + c0 + 4]);
    ((float4*)dst)[i] = v;
}

// ---------------- aux kernels --------------------------------------------
__global__ void inv_kernel() {
    const int i = blockIdx.x * 256 + threadIdx.x;
    g_inv[i] = 1.f / (sqrtf(g_ss[i]) + 1e-8f);
}
__global__ void msum_kernel(const float* __restrict__ mask) {
    int w = threadIdx.x >> 5, lane = threadIdx.x & 31;
    if (w >= BATCH) return;
    float s = 0.f;
    for (int n = lane; n < SEQ; n += 32) s += mask[n * BATCH + w];
    #pragma unroll
    for (int o = 16; o > 0; o >>= 1) s += __shfl_xor_sync(0xffffffffu, s, o);
    if (lane == 0) g_msum[w] = s;
}
__global__ void ws_kernel(const float* __restrict__ mask) {
    __shared__ float coef[256];
    int b = blockIdx.x, n0 = blockIdx.y * 256, tid = threadIdx.x;
    coef[tid] = mask[(n0 + tid) * BATCH + b] * g_inv[b * SEQ + n0 + tid];
    __syncthreads();
    float acc[4] = {0.f, 0.f, 0.f, 0.f};
    const float* base = g_xp + (size_t)(b * SEQ + n0) * NDIM;
    for (int j = 0; j < 256; j++) {
        float cf = coef[j];
        const float* r = base + (size_t)j * NDIM;
        #pragma unroll
        for (int i = 0; i < 4; i++) acc[i] += cf * r[tid + i * 256];
    }
    #pragma unroll
    for (int i = 0; i < 4; i++) atomicAdd(&g_ws[b * NDIM + tid + i * 256], acc[i]);
}
__global__ void att_kernel() {
    int row = blockIdx.x * 8 + (threadIdx.x >> 5);
    int lane = threadIdx.x & 31;
    int b = row >> 11;
    const float* xr = g_xp + (size_t)row * NDIM;
    const float* w  = g_ws + b * NDIM;
    float d = 0.f;
    #pragma unroll 8
    for (int i = lane; i < NDIM; i += 32) d += xr[i] * w[i];
    #pragma unroll
    for (int o = 16; o > 0; o >>= 1) d += __shfl_xor_sync(0xffffffffu, d, o);
    if (lane == 0) g_att[row] = g_inv[row] * d / g_msum[b];
}

// ---------------- launch -------------------------------------------------
extern "C" void kernel_launch(void* const* d_in, const int* in_sizes, int n_in,
                              void* d_out, int out_size) {
    const float* x    = (const float*)d_in[0];
    const float* mask = (const float*)d_in[1];
    const float* Wp   = (const float*)d_in[2];
    const float* bp   = (const float*)d_in[3];
    const float* Wv   = (const float*)d_in[4];
    const float* bv   = (const float*)d_in[5];
    float* out = (float*)d_out;

    cudaFuncSetAttribute(gemm_relu_kernel<false>, cudaFuncAttributeMaxDynamicSharedMemorySize, SMEM_BYTES);
    cudaFuncSetAttribute(gemm_relu_kernel<true>,  cudaFuncAttributeMaxDynamicSharedMemorySize, SMEM_BYTES);

    float *xf, *wpf, *wvf;
    cudaGetSymbolAddress((void**)&xf,  g_xf);
    cudaGetSymbolAddress((void**)&wpf, g_wpf);
    cudaGetSymbolAddress((void**)&wvf, g_wvf);

    dim3 ggrid(NDIM / 128, M_ROWS / 128);   // (8, 256)

    cvtA_kernel<<<(M_ROWS * KDIM / 4) / 256, 256>>>(x);               // 0
    cvtB_kernel<<<(NDIM * KDIM / 4) / 256, 256>>>(Wp, wpf);           // 1
    cvtB_kernel<<<(NDIM * KDIM / 4) / 256, 256>>>(Wv, wvf);           // 2
    gemm_relu_kernel<false><<<ggrid, 128, SMEM_BYTES>>>(xf, wpf, bp, nullptr);  // 3
    inv_kernel<<<M_ROWS / 256, 256>>>();                              // 4
    msum_kernel<<<1, 512>>>(mask);                                    // 5
    ws_kernel<<<dim3(BATCH, SEQ / 256), 256>>>(mask);                 // 6
    att_kernel<<<M_ROWS / 8, 256>>>();                                // 7
    gemm_relu_kernel<true><<<ggrid, 128, SMEM_BYTES>>>(xf, wvf, bv, out);  // 8
}